// round 6
// baseline (speedup 1.0000x reference)
#include <cuda_runtime.h>
#include <math.h>

// Problem constants
#define E_EDGES 100000
#define S_MEM   16
#define D_DIM   128
#define C_CLS   6
#define H_HEADS 4
#define M_IND   4
#define G_EDGES 8                       // edges per CTA
#define ROWS    (G_EDGES * S_MEM)       // 128 rows per CTA
#define NTHREADS 256

#define SCALE_INV_SQRT_DV 0.08838834764831845f  // 1/sqrt(128)

// Shared memory plan (floats):
//  bufA [128][128]  gathered V; later out = O + relu(O@Wo1)
//  bufB [128][128]  K0; later rows 96..127 = Hset, rows 0..31 = V1
//  bufC [128][128]  V0; later Q1; then O (attn1 out, in place)
//  sS1  [ 32][128]  O0; later K1
//  sW   [ 16][128]  staged weight k-tile
//  sScr [2048]      attention scores / staged Wout+bout
#define SMEM_FLOATS (3*ROWS*D_DIM + 32*D_DIM + 16*D_DIM + 2048)
#define SMEM_BYTES  (SMEM_FLOATS * 4)

__device__ __align__(16) float g_Iq[M_IND * D_DIM];  // I @ Wq0 + bq0

// ---- packed f32x2 helpers (Blackwell) ----
__device__ __forceinline__ unsigned long long pack_dup(float x) {
    unsigned long long r;
    unsigned int xi = __float_as_uint(x);
    asm("mov.b64 %0, {%1, %1};" : "=l"(r) : "r"(xi));
    return r;
}
__device__ __forceinline__ void ffma2(unsigned long long& acc,
                                      unsigned long long a,
                                      unsigned long long b) {
    asm("fma.rn.f32x2 %0, %1, %2, %0;" : "+l"(acc) : "l"(a), "l"(b));
}
__device__ __forceinline__ float2 unpack2(unsigned long long v) {
    float2 f;
    asm("mov.b64 {%0, %1}, %2;" : "=f"(f.x), "=f"(f.y) : "l"(v));
    return f;
}

// -------- prolog: Iq = I @ Wq0 + bq0 --------
__global__ void iq_kernel(const float* __restrict__ I,
                          const float* __restrict__ Wq,
                          const float* __restrict__ bq) {
    int idx = blockIdx.x * blockDim.x + threadIdx.x;
    if (idx >= M_IND * D_DIM) return;
    int qi = idx / D_DIM, d = idx % D_DIM;
    float acc = bq[d];
#pragma unroll 8
    for (int k = 0; k < D_DIM; k++) acc += I[qi * D_DIM + k] * Wq[k * D_DIM + d];
    g_Iq[idx] = acc;
}

// -------- SMEM-tile GEMM via packed f32x2: Y = X @ W (+bias, epilogue) --------
template<int MROWS, bool SKIP_RELU>
__device__ __forceinline__ void gemm_tile(
    const float* __restrict__ Xs,          // smem [MROWS][128]
    const float* __restrict__ Wg,          // gmem [128][128]
    const float* __restrict__ bg,          // gmem [128]
    float* __restrict__ Ys,                // smem [MROWS][128]
    const float* __restrict__ Sk,          // smem skip (for SKIP_RELU)
    float* __restrict__ sW, int tid)
{
    constexpr int RPT = MROWS / 16;        // rows per thread
    const int tx = tid & 15;               // 16 col groups of 8 (= 4 f32x2 pairs)
    const int ty = tid >> 4;               // 16 row groups of RPT

    unsigned long long acc[RPT][4];
#pragma unroll
    for (int i = 0; i < RPT; i++)
#pragma unroll
        for (int j = 0; j < 4; j++) acc[i][j] = 0ull;

    float bias[8];
#pragma unroll
    for (int j = 0; j < 8; j++) bias[j] = bg[tx * 8 + j];

#pragma unroll 1
    for (int kt = 0; kt < 8; kt++) {
        __syncthreads();
        // stage W rows [kt*16, kt*16+16): 2048 floats, coalesced scalar loads
#pragma unroll
        for (int k = 0; k < 8; k++) {
            sW[tid + k * 256] = Wg[kt * 2048 + tid + k * 256];
        }
        __syncthreads();

#pragma unroll
        for (int kk = 0; kk < 16; kk += 4) {
            float4 av[RPT];
#pragma unroll
            for (int i = 0; i < RPT; i++) {
                av[i] = *reinterpret_cast<const float4*>(
                    &Xs[(ty * RPT + i) * D_DIM + kt * 16 + kk]);
            }
#pragma unroll
            for (int q = 0; q < 4; q++) {
                const ulonglong2* bp = reinterpret_cast<const ulonglong2*>(
                    &sW[(kk + q) * D_DIM + tx * 8]);
                ulonglong2 b01 = bp[0];
                ulonglong2 b23 = bp[1];
#pragma unroll
                for (int i = 0; i < RPT; i++) {
                    float as = (q == 0) ? av[i].x : (q == 1) ? av[i].y
                             : (q == 2) ? av[i].z : av[i].w;
                    unsigned long long ap = pack_dup(as);
                    ffma2(acc[i][0], ap, b01.x);
                    ffma2(acc[i][1], ap, b01.y);
                    ffma2(acc[i][2], ap, b23.x);
                    ffma2(acc[i][3], ap, b23.y);
                }
            }
        }
    }

    // epilogue
#pragma unroll
    for (int i = 0; i < RPT; i++) {
        int row = ty * RPT + i;
        float o[8];
#pragma unroll
        for (int j = 0; j < 4; j++) {
            float2 v = unpack2(acc[i][j]);
            o[2 * j]     = v.x + bias[2 * j];
            o[2 * j + 1] = v.y + bias[2 * j + 1];
        }
        if (SKIP_RELU) {
#pragma unroll
            for (int j = 0; j < 8; j++)
                o[j] = Sk[row * D_DIM + tx * 8 + j] + fmaxf(o[j], 0.f);
        }
        *reinterpret_cast<float4*>(&Ys[row * D_DIM + tx * 8])     = make_float4(o[0], o[1], o[2], o[3]);
        *reinterpret_cast<float4*>(&Ys[row * D_DIM + tx * 8 + 4]) = make_float4(o[4], o[5], o[6], o[7]);
    }
    __syncthreads();
}

// -------- main fused kernel: 8 edges per CTA --------
extern "C" __global__ void __launch_bounds__(NTHREADS)
whatsnet_kernel(const float* __restrict__ vfeat,
                const int*   __restrict__ member_idx,
                const int*   __restrict__ labels,
                const float* __restrict__ Wout, const float* __restrict__ bout,
                const float* __restrict__ Wk0,  const float* __restrict__ bk0,
                const float* __restrict__ Wv0,  const float* __restrict__ bv0,
                const float* __restrict__ Wo0,  const float* __restrict__ bo0,
                const float* __restrict__ Wq1,  const float* __restrict__ bq1,
                const float* __restrict__ Wk1,  const float* __restrict__ bk1,
                const float* __restrict__ Wv1,  const float* __restrict__ bv1,
                const float* __restrict__ Wo1,  const float* __restrict__ bo1,
                float* __restrict__ out,
                int n_nodes,
                long long out_capacity)
{
    extern __shared__ float smem[];
    float* bufA   = smem;
    float* bufB   = bufA + ROWS * D_DIM;
    float* bufC   = bufB + ROWS * D_DIM;
    float* sS1    = bufC + ROWS * D_DIM;   // 32*128
    float* sW     = sS1 + 32 * D_DIM;      // 16*128
    float* sScr   = sW + 16 * D_DIM;       // 2048

    const int tid = threadIdx.x;
    const int blk = blockIdx.x;
    const int rowbase = blk * ROWS;

    // ---- 1. gather vfeat[member_idx] -> bufA (clamped, coalesced) ----
    {
        int warp = tid >> 5, lane = tid & 31;
        for (int r = warp; r < ROWS; r += 8) {
            int n = member_idx[rowbase + r];
            if (n < 0) n = 0;
            if (n >= n_nodes) n = n_nodes - 1;
            const float* src = vfeat + (size_t)n * D_DIM;
#pragma unroll
            for (int k = 0; k < 4; k++)
                bufA[r * D_DIM + lane + k * 32] = src[lane + k * 32];
        }
    }
    __syncthreads();

    // ---- 2/3. K0 -> bufB ; V0 -> bufC ----
    gemm_tile<128, false>(bufA, Wk0, bk0, bufB, nullptr, sW, tid);
    gemm_tile<128, false>(bufA, Wv0, bv0, bufC, nullptr, sW, tid);

    // ---- 4. attention0: scores idx = ((e*4+h)*4+qi)*16 + s  (128 rows x 16) ----
#pragma unroll 1
    for (int it = 0; it < 8; it++) {
        int idx = tid + it * 256;
        int s  = idx & 15;
        int qi = (idx >> 4) & 3;
        int h  = (idx >> 6) & 3;
        int e  = idx >> 8;
        const float4* qv = reinterpret_cast<const float4*>(&g_Iq[qi * D_DIM + h * 32]);
        const float4* kv = reinterpret_cast<const float4*>(&bufB[(e * 16 + s) * D_DIM + h * 32]);
        float dot = 0.f;
#pragma unroll
        for (int d4 = 0; d4 < 8; d4++) {
            float4 q = qv[d4], k = kv[d4];
            dot += q.x * k.x + q.y * k.y + q.z * k.z + q.w * k.w;
        }
        sScr[idx] = dot * SCALE_INV_SQRT_DV;
    }
    __syncthreads();
    // softmax over s=16: 128 rows
    if (tid < 128) {
        float* p = &sScr[tid * 16];
        float mx = p[0];
#pragma unroll
        for (int i = 1; i < 16; i++) mx = fmaxf(mx, p[i]);
        float sum = 0.f;
#pragma unroll
        for (int i = 0; i < 16; i++) { float ex = expf(p[i] - mx); p[i] = ex; sum += ex; }
        float inv = 1.f / sum;
#pragma unroll
        for (int i = 0; i < 16; i++) p[i] *= inv;
    }
    __syncthreads();
    // O0[e*4+qi][d] = Iq[qi][d] + sum_s A * V0  -> sS1 (32 rows)
#pragma unroll 1
    for (int it = 0; it < 16; it++) {
        int idx = tid + it * 256;          // row(32)*128 + d
        int d = idx & 127;
        int row = idx >> 7;
        int qi = row & 3, e = row >> 2;
        int h = d >> 5;
        float o = g_Iq[qi * D_DIM + d];
        const float* A  = &sScr[((e * 4 + h) * 4 + qi) * 16];
        const float* vv = &bufC[(e * 16) * D_DIM + d];
#pragma unroll
        for (int s = 0; s < 16; s++) o += A[s] * vv[s * D_DIM];
        sS1[idx] = o;
    }
    __syncthreads();

    // ---- 5. Hset = O0 + relu(O0@Wo0+bo0) -> bufB rows 96..127 ----
    gemm_tile<32, true>(sS1, Wo0, bo0, bufB + 96 * D_DIM, sS1, sW, tid);

    // ---- 6. Q1 = V@Wq1+bq1 -> bufC ----
    gemm_tile<128, false>(bufA, Wq1, bq1, bufC, nullptr, sW, tid);

    // ---- 7. K1 -> sS1 ; V1 -> bufB rows 0..31 ----
    gemm_tile<32, false>(bufB + 96 * D_DIM, Wk1, bk1, sS1, nullptr, sW, tid);
    gemm_tile<32, false>(bufB + 96 * D_DIM, Wv1, bv1, bufB, nullptr, sW, tid);

    // ---- 8. attention1: scores idx = ((e*4+h)*16+q)*4 + k  (512 rows x 4) ----
#pragma unroll 1
    for (int it = 0; it < 8; it++) {
        int idx = tid + it * 256;
        int k = idx & 3;
        int q = (idx >> 2) & 15;
        int h = (idx >> 6) & 3;
        int e = idx >> 8;
        const float4* qv = reinterpret_cast<const float4*>(&bufC[(e * 16 + q) * D_DIM + h * 32]);
        const float4* kv = reinterpret_cast<const float4*>(&sS1[(e * 4 + k) * D_DIM + h * 32]);
        float dot = 0.f;
#pragma unroll
        for (int d4 = 0; d4 < 8; d4++) {
            float4 qq = qv[d4], kk = kv[d4];
            dot += qq.x * kk.x + qq.y * kk.y + qq.z * kk.z + qq.w * kk.w;
        }
        sScr[idx] = dot * SCALE_INV_SQRT_DV;
    }
    __syncthreads();
    // softmax over k=4: 512 rows
    for (int r = tid; r < 512; r += 256) {
        float* p = &sScr[r * 4];
        float mx = fmaxf(fmaxf(p[0], p[1]), fmaxf(p[2], p[3]));
        float e0 = expf(p[0] - mx), e1 = expf(p[1] - mx), e2 = expf(p[2] - mx), e3 = expf(p[3] - mx);
        float inv = 1.f / (e0 + e1 + e2 + e3);
        p[0] = e0 * inv; p[1] = e1 * inv; p[2] = e2 * inv; p[3] = e3 * inv;
    }
    __syncthreads();
    // O = Q1 + A1@V1, in place in bufC
#pragma unroll 1
    for (int it = 0; it < 64; it++) {
        int idx = tid + it * 256;          // row(128)*128 + d
        int d = idx & 127;
        int row = idx >> 7;
        int q = row & 15, e = row >> 4;
        int h = d >> 5;
        float o = bufC[idx];
        const float* A  = &sScr[((e * 4 + h) * 16 + q) * 4];
        const float* vv = &bufB[(e * 4) * D_DIM + d];
#pragma unroll
        for (int k = 0; k < 4; k++) o += A[k] * vv[k * D_DIM];
        bufC[idx] = o;
    }
    __syncthreads();

    // ---- 9. out = O + relu(O@Wo1+bo1) -> bufA ----
    gemm_tile<128, true>(bufC, Wo1, bo1, bufA, bufC, sW, tid);

    // ---- 10. logits = out@Wout + bout ----
    for (int i = tid; i < D_DIM * C_CLS; i += 256) sScr[i] = Wout[i];
    if (tid < C_CLS) sScr[D_DIM * C_CLS + tid] = bout[tid];
    __syncthreads();
#pragma unroll 1
    for (int it = 0; it < 3; it++) {
        int idx = tid + it * 256;          // r*6 + c
        int c = idx % C_CLS, r = idx / C_CLS;
        float acc = sScr[D_DIM * C_CLS + c];
        const float4* xr = reinterpret_cast<const float4*>(&bufA[r * D_DIM]);
#pragma unroll
        for (int k4 = 0; k4 < 32; k4++) {
            float4 x = xr[k4];
            acc += x.x * sScr[(k4 * 4 + 0) * C_CLS + c]
                 + x.y * sScr[(k4 * 4 + 1) * C_CLS + c]
                 + x.z * sScr[(k4 * 4 + 2) * C_CLS + c]
                 + x.w * sScr[(k4 * 4 + 3) * C_CLS + c];
        }
        long long off = (long long)(rowbase + r) * C_CLS + c;
        if (off < out_capacity) out[off] = acc;
    }

    // ---- 11. labels passthrough (only if the tuple fits) ----
    long long lab_base = (long long)E_EDGES * S_MEM * C_CLS;
    if (out_capacity >= lab_base + (long long)E_EDGES * S_MEM) {
        for (int r = tid; r < ROWS; r += 256) {
            out[lab_base + rowbase + r] = (float)labels[rowbase + r];
        }
    }
}

extern "C" void kernel_launch(void* const* d_in, const int* in_sizes, int n_in,
                              void* d_out, int out_size) {
    // --- size-based input identification (robust to slot permutation) ---
    const float* Ws[8] = {0,0,0,0,0,0,0,0};
    const float* Bs[8] = {0,0,0,0,0,0,0,0};
    const float* vfeat = 0; const float* Iin = 0;
    const float* Wout = 0;  const float* bout = 0;
    const int* member_idx = 0; const int* labels = 0;
    int wi = 0, bi = 0;
    int n_nodes = 500000;
    for (int i = 0; i < n_in; i++) {
        int sz = in_sizes[i];
        if (sz == 500000 * 128)      { vfeat = (const float*)d_in[i]; n_nodes = sz / D_DIM; }
        else if (sz == E_EDGES * S_MEM) {
            if (!member_idx) member_idx = (const int*)d_in[i];
            else if (!labels) labels = (const int*)d_in[i];
        }
        else if (sz == M_IND * D_DIM) Iin = (const float*)d_in[i];
        else if (sz == D_DIM * C_CLS) Wout = (const float*)d_in[i];
        else if (sz == C_CLS)         bout = (const float*)d_in[i];
        else if (sz == D_DIM * D_DIM) { if (wi < 8) Ws[wi++] = (const float*)d_in[i]; }
        else if (sz == D_DIM)         { if (bi < 8) Bs[bi++] = (const float*)d_in[i]; }
    }
    if (!vfeat || !member_idx || !labels || !Iin || !Wout || !bout || wi != 8 || bi != 8) {
        vfeat      = (const float*)d_in[0];
        member_idx = (const int*)  d_in[1];
        labels     = (const int*)  d_in[2];
        Iin        = (const float*)d_in[3];
        Wout       = (const float*)d_in[4];
        bout       = (const float*)d_in[5];
        for (int j = 0; j < 8; j++) {
            Ws[j] = (const float*)d_in[6 + 2 * j];
            Bs[j] = (const float*)d_in[7 + 2 * j];
        }
        n_nodes = in_sizes[0] / D_DIM;
    }
    // order within size class: Wq0,Wk0,Wv0,Wo0,Wq1,Wk1,Wv1,Wo1
    const float *Wq0 = Ws[0], *Wk0 = Ws[1], *Wv0 = Ws[2], *Wo0 = Ws[3];
    const float *Wq1 = Ws[4], *Wk1 = Ws[5], *Wv1 = Ws[6], *Wo1 = Ws[7];
    const float *bq0 = Bs[0], *bk0 = Bs[1], *bv0 = Bs[2], *bo0 = Bs[3];
    const float *bq1 = Bs[4], *bk1 = Bs[5], *bv1 = Bs[6], *bo1 = Bs[7];

    float* out = (float*)d_out;

    cudaFuncSetAttribute(whatsnet_kernel, cudaFuncAttributeMaxDynamicSharedMemorySize, SMEM_BYTES);

    iq_kernel<<<2, 256>>>(Iin, Wq0, bq0);

    whatsnet_kernel<<<E_EDGES / G_EDGES, NTHREADS, SMEM_BYTES>>>(
        vfeat, member_idx, labels, Wout, bout,
        Wk0, bk0, Wv0, bv0, Wo0, bo0,
        Wq1, bq1, Wk1, bk1, Wv1, bv1, Wo1, bo1,
        out, n_nodes, (long long)out_size);
}

// round 8
// speedup vs baseline: 2.3508x; 2.3508x over previous
#include <cuda_runtime.h>
#include <cuda_bf16.h>
#include <math.h>
#include <stdint.h>

#define E_EDGES 100000
#define S_MEM   16
#define D_DIM   128
#define C_CLS   6
#define M_IND   4
#define ROWS    128
#define NTHREADS 256
#define SCALE_INV 0.08838834764831845f

// SMEM byte offsets
#define OFF_XH  0
#define OFF_XL  32768
#define OFF_WH  65536
#define OFF_WL  98304
#define OFF_SF  131072                 // f32 [128][132]
#define SF_STR  132
#define OFF_SSM (OFF_SF + 128*SF_STR*4)    // f32 [32][132]
#define OFF_BIAS (OFF_SSM + 32*SF_STR*4)   // f32 [6][128]
#define OFF_IQ  (OFF_BIAS + 6*128*4)       // f32 [512]
#define OFF_IQB (OFF_IQ + 2048)            // f32 [16]
#define OFF_WOUT (OFF_IQB + 64)            // f32 [776]
#define OFF_SCR (OFF_WOUT + 3104)          // f32 [2048]
#define SMEM_TOTAL (OFF_SCR + 8192)        // 232032 <= 232448

__device__ __align__(16) float g_Iq[M_IND * D_DIM];
__device__ __align__(16) float g_Iqb[16];
// weight images, [n][k] row-major bf16 with 16B-chunk XOR swizzle
// widx: 0=Wk0 1=Wv0 2=Wq1 3=Wo0 4=Wk1 5=Wv1 6=Wo1
__device__ __align__(16) __nv_bfloat16 g_WH[7][16384];
__device__ __align__(16) __nv_bfloat16 g_WL[7][16384];

// bf16 image byte offset with chunk swizzle: row r, col c (128 cols/row = 16 chunks of 16B)
__host__ __device__ __forceinline__ int imgoff(int r, int c) {
    return r * 256 + (((c >> 3) ^ (r & 7)) << 4) + ((c & 7) << 1);
}

__device__ __forceinline__ uint32_t cvta_s(const void* p) {
    uint32_t a;
    asm("{ .reg .u64 t; cvta.to.shared.u64 t, %1; cvt.u32.u64 %0, t; }" : "=r"(a) : "l"(p));
    return a;
}
__device__ __forceinline__ void ldsm4(uint32_t* a, uint32_t addr) {
    asm volatile("ldmatrix.sync.aligned.m8n8.x4.shared.b16 {%0,%1,%2,%3}, [%4];"
        : "=r"(a[0]), "=r"(a[1]), "=r"(a[2]), "=r"(a[3]) : "r"(addr));
}
__device__ __forceinline__ void ldsm2(uint32_t* b, uint32_t addr) {
    asm volatile("ldmatrix.sync.aligned.m8n8.x2.shared.b16 {%0,%1}, [%2];"
        : "=r"(b[0]), "=r"(b[1]) : "r"(addr));
}
__device__ __forceinline__ void mma16816(float* c, const uint32_t* a, const uint32_t* b) {
    asm volatile("mma.sync.aligned.m16n8k16.row.col.f32.bf16.bf16.f32 "
        "{%0,%1,%2,%3}, {%4,%5,%6,%7}, {%8,%9}, {%0,%1,%2,%3};"
        : "+f"(c[0]), "+f"(c[1]), "+f"(c[2]), "+f"(c[3])
        : "r"(a[0]), "r"(a[1]), "r"(a[2]), "r"(a[3]), "r"(b[0]), "r"(b[1]));
}
__device__ __forceinline__ void img_st(char* sm, int r, int c, float v) {
    int i = imgoff(r, c);
    __nv_bfloat16 h = __float2bfloat16(v);
    *(__nv_bfloat16*)(sm + OFF_XH + i) = h;
    *(__nv_bfloat16*)(sm + OFF_XL + i) = __float2bfloat16(v - __bfloat162float(h));
}
__device__ __forceinline__ void img_st2(char* sm, int r, int c, float v0, float v1) {
    int i = imgoff(r, c);                 // c even, pair within chunk
    __nv_bfloat162 h, l;
    h.x = __float2bfloat16(v0); h.y = __float2bfloat16(v1);
    l.x = __float2bfloat16(v0 - __bfloat162float(h.x));
    l.y = __float2bfloat16(v1 - __bfloat162float(h.y));
    *(__nv_bfloat162*)(sm + OFF_XH + i) = h;
    *(__nv_bfloat162*)(sm + OFF_XL + i) = l;
}

// ---------------- prologs ----------------
__global__ void iq_kernel(const float* __restrict__ I, const float* __restrict__ Wq,
                          const float* __restrict__ bq) {
    int idx = blockIdx.x * blockDim.x + threadIdx.x;
    if (idx >= M_IND * D_DIM) return;
    int qi = idx / D_DIM, d = idx % D_DIM;
    float acc = bq[d];
    for (int k = 0; k < D_DIM; k++) acc += I[qi * D_DIM + k] * Wq[k * D_DIM + d];
    g_Iq[idx] = acc;
}
__global__ void iqb_kernel(const float* __restrict__ bk0) {
    int t = threadIdx.x;
    if (t < 16) {
        int qi = t >> 2, h = t & 3;
        float s = 0.f;
        for (int j = 0; j < 32; j++) s += g_Iq[qi * 128 + h * 32 + j] * bk0[h * 32 + j];
        g_Iqb[t] = s;
    }
}
__global__ void wconv_kernel(const float* W0, const float* W1, const float* W2, const float* W3,
                             const float* W4, const float* W5, const float* W6) {
    const float* W;
    int m = blockIdx.x;
    switch (m) { case 0: W = W0; break; case 1: W = W1; break; case 2: W = W2; break;
                 case 3: W = W3; break; case 4: W = W4; break; case 5: W = W5; break;
                 default: W = W6; }
    for (int i = threadIdx.x; i < 16384; i += blockDim.x) {
        int n = i >> 7, k = i & 127;
        float w = W[k * 128 + n];          // B[n][k] = W[k][n]
        __nv_bfloat16 h = __float2bfloat16(w);
        int idx = n * 128 + (((k >> 3) ^ (n & 7)) << 3) + (k & 7);
        g_WH[m][idx] = h;
        g_WL[m][idx] = __float2bfloat16(w - __bfloat162float(h));
    }
}

// stage weight images to SMEM (sync before+after)
__device__ __forceinline__ void load_w(char* sm, int widx, int tid) {
    __syncthreads();
    const float4* sh = (const float4*)g_WH[widx];
    const float4* sl = (const float4*)g_WL[widx];
    float4* dh = (float4*)(sm + OFF_WH);
    float4* dl = (float4*)(sm + OFF_WL);
#pragma unroll
    for (int i = 0; i < 8; i++) {
        dh[tid + i * 256] = sh[tid + i * 256];
        dl[tid + i * 256] = sl[tid + i * 256];
    }
    __syncthreads();
}

// 128x128x128 GEMM, 3-pass bf16 split; warp = (rowgroup wid>>1, colgroup wid&1)
__device__ __forceinline__ void gemm128(uint32_t xh, uint32_t xl, uint32_t wh, uint32_t wl,
                                        int wid, int lane, float acc[2][8][4]) {
    const int rg = wid >> 1, cg = wid & 1;
    const int lr = lane & 15, lh = lane >> 4;
    const int bn = (lane & 7), bh2 = (lane >> 3) & 1;
#pragma unroll
    for (int ks = 0; ks < 8; ks++) {
        uint32_t ah[2][4], al[2][4];
#pragma unroll
        for (int rt = 0; rt < 2; rt++) {
            int r = rg * 32 + rt * 16 + lr;
            uint32_t off = (uint32_t)(r * 256 + (((ks * 2 + lh) ^ (r & 7)) << 4));
            ldsm4(ah[rt], xh + off);
            ldsm4(al[rt], xl + off);
        }
#pragma unroll
        for (int nt = 0; nt < 8; nt++) {
            int n = cg * 64 + nt * 8 + bn;
            uint32_t boff = (uint32_t)(n * 256 + (((ks * 2 + bh2) ^ (n & 7)) << 4));
            uint32_t bhf[2], blf[2];
            ldsm2(bhf, wh + boff);
            ldsm2(blf, wl + boff);
#pragma unroll
            for (int rt = 0; rt < 2; rt++) {
                mma16816(acc[rt][nt], ah[rt], bhf);
                mma16816(acc[rt][nt], al[rt], bhf);
                mma16816(acc[rt][nt], ah[rt], blf);
            }
        }
    }
}

// 32x128x128 GEMM; warp = (rowtile wid>>2, colgroup wid&3)
__device__ __forceinline__ void gemm32(uint32_t xh, uint32_t xl, uint32_t wh, uint32_t wl,
                                       int wid, int lane, float acc[4][4]) {
    const int rt = wid >> 2, cg = wid & 3;
    const int lr = lane & 15, lh = lane >> 4;
    const int bn = (lane & 7), bh2 = (lane >> 3) & 1;
#pragma unroll
    for (int ks = 0; ks < 8; ks++) {
        uint32_t ah[4], al[4];
        int r = rt * 16 + lr;
        uint32_t off = (uint32_t)(r * 256 + (((ks * 2 + lh) ^ (r & 7)) << 4));
        ldsm4(ah, xh + off);
        ldsm4(al, xl + off);
#pragma unroll
        for (int nt = 0; nt < 4; nt++) {
            int n = cg * 32 + nt * 8 + bn;
            uint32_t boff = (uint32_t)(n * 256 + (((ks * 2 + bh2) ^ (n & 7)) << 4));
            uint32_t bhf[2], blf[2];
            ldsm2(bhf, wh + boff);
            ldsm2(blf, wl + boff);
            mma16816(acc[nt], ah, bhf);
            mma16816(acc[nt], al, bhf);
            mma16816(acc[nt], ah, blf);
        }
    }
}

extern "C" __global__ void __launch_bounds__(NTHREADS)
whatsnet_mma(const float* __restrict__ vfeat, const int* __restrict__ member_idx,
             const int* __restrict__ labels,
             const float* __restrict__ Wout, const float* __restrict__ bout,
             const float* __restrict__ bv0, const float* __restrict__ bo0,
             const float* __restrict__ bq1, const float* __restrict__ bk1,
             const float* __restrict__ bv1, const float* __restrict__ bo1,
             float* __restrict__ out, int n_nodes, long long out_capacity)
{
    extern __shared__ char sm[];
    const int tid = threadIdx.x;
    const int wid = tid >> 5, lane = tid & 31;
    const int rowbase = blockIdx.x * ROWS;
    const uint32_t sb = cvta_s(sm);
    const uint32_t xh = sb + OFF_XH, xl = sb + OFF_XL;
    const uint32_t wh = sb + OFF_WH, wl = sb + OFF_WL;

    float* sF   = (float*)(sm + OFF_SF);
    float* sSm  = (float*)(sm + OFF_SSM);
    float* sBias= (float*)(sm + OFF_BIAS);
    float* sIq  = (float*)(sm + OFF_IQ);
    float* sIqb = (float*)(sm + OFF_IQB);
    float* sWo  = (float*)(sm + OFF_WOUT);
    float* sScr = (float*)(sm + OFF_SCR);
    float* sV1f = (float*)(sm + OFF_XH);   // 32x128 f32 scratch, valid only after V1 gemm

    // constants
    if (tid < 128) {
        sBias[0 * 128 + tid] = bv0[tid];
        sBias[1 * 128 + tid] = bo0[tid];
        sBias[2 * 128 + tid] = bq1[tid];
        sBias[3 * 128 + tid] = bk1[tid];
        sBias[4 * 128 + tid] = bv1[tid];
        sBias[5 * 128 + tid] = bo1[tid];
    }
    for (int i = tid; i < 512; i += NTHREADS) sIq[i] = g_Iq[i];
    if (tid < 16) sIqb[tid] = g_Iqb[tid];
    for (int i = tid; i < 768; i += NTHREADS) sWo[i] = Wout[i];
    if (tid < 6) sWo[768 + tid] = bout[tid];

    // gather -> X images
    for (int r = wid; r < ROWS; r += 8) {
        int n = member_idx[rowbase + r];
        if (n < 0) n = 0;
        if (n >= n_nodes) n = n_nodes - 1;
        const float* src = vfeat + (size_t)n * D_DIM;
#pragma unroll
        for (int k = 0; k < 4; k++) {
            int c = lane + k * 32;
            img_st(sm, r, c, src[c]);
        }
    }

    const int l4 = lane >> 2, c2 = (lane & 3) * 2;

    // ===== K0 = X@Wk0 -> sF (raw) =====
    {
        load_w(sm, 0, tid);
        float acc[2][8][4] = {};
        gemm128(xh, xl, wh, wl, wid, lane, acc);
        int rg = wid >> 1, cg = wid & 1;
#pragma unroll
        for (int rt = 0; rt < 2; rt++)
#pragma unroll
            for (int nt = 0; nt < 8; nt++) {
                int r = rg * 32 + rt * 16 + l4, c = cg * 64 + nt * 8 + c2;
                sF[r * SF_STR + c]       = acc[rt][nt][0];
                sF[r * SF_STR + c + 1]   = acc[rt][nt][1];
                sF[(r + 8) * SF_STR + c]     = acc[rt][nt][2];
                sF[(r + 8) * SF_STR + c + 1] = acc[rt][nt][3];
            }
    }
    __syncthreads();

    // scores0: ((e*4+h)*4+qi)*16+s
#pragma unroll 1
    for (int it = 0; it < 8; it++) {
        int idx = tid + it * 256;
        int s = idx & 15, qi = (idx >> 4) & 3, h = (idx >> 6) & 3, e = idx >> 8;
        const float4* qv = (const float4*)&sIq[qi * 128 + h * 32];
        const float4* kv = (const float4*)&sF[(e * 16 + s) * SF_STR + h * 32];
        float dot = sIqb[qi * 4 + h];
#pragma unroll
        for (int d4 = 0; d4 < 8; d4++) {
            float4 q = qv[d4], k = kv[d4];
            dot += q.x * k.x + q.y * k.y + q.z * k.z + q.w * k.w;
        }
        sScr[idx] = dot * SCALE_INV;
    }
    __syncthreads();

    // ===== V0 = X@Wv0 + bv0 -> sF =====
    {
        load_w(sm, 1, tid);
        float acc[2][8][4] = {};
        gemm128(xh, xl, wh, wl, wid, lane, acc);
        __syncthreads();                      // scores0 readers done with K0 in sF
        int rg = wid >> 1, cg = wid & 1;
#pragma unroll
        for (int rt = 0; rt < 2; rt++)
#pragma unroll
            for (int nt = 0; nt < 8; nt++) {
                int r = rg * 32 + rt * 16 + l4, c = cg * 64 + nt * 8 + c2;
                sF[r * SF_STR + c]       = acc[rt][nt][0] + sBias[c];
                sF[r * SF_STR + c + 1]   = acc[rt][nt][1] + sBias[c + 1];
                sF[(r + 8) * SF_STR + c]     = acc[rt][nt][2] + sBias[c];
                sF[(r + 8) * SF_STR + c + 1] = acc[rt][nt][3] + sBias[c + 1];
            }
    }
    __syncthreads();

    // softmax0 over s=16, 128 rows
    if (tid < 128) {
        float* p = &sScr[tid * 16];
        float mx = p[0];
#pragma unroll
        for (int i = 1; i < 16; i++) mx = fmaxf(mx, p[i]);
        float sum = 0.f;
#pragma unroll
        for (int i = 0; i < 16; i++) { float ex = expf(p[i] - mx); p[i] = ex; sum += ex; }
        float inv = 1.f / sum;
#pragma unroll
        for (int i = 0; i < 16; i++) p[i] *= inv;
    }
    __syncthreads();

    // O0 = Iq + A @ V0f -> sSm (32 rows)
#pragma unroll 1
    for (int it = 0; it < 16; it++) {
        int idx = tid + it * 256;
        int d = idx & 127, row = idx >> 7;
        int qi = row & 3, e = row >> 2, h = d >> 5;
        float o = sIq[qi * 128 + d];
        const float* A = &sScr[((e * 4 + h) * 4 + qi) * 16];
        const float* vv = &sF[(e * 16) * SF_STR + d];
#pragma unroll
        for (int s = 0; s < 16; s++) o += A[s] * vv[s * SF_STR];
        sSm[row * SF_STR + d] = o;
    }
    __syncthreads();

    // ===== Q1 = X@Wq1 + bq1 -> sF =====
    {
        load_w(sm, 2, tid);
        float acc[2][8][4] = {};
        gemm128(xh, xl, wh, wl, wid, lane, acc);
        int rg = wid >> 1, cg = wid & 1;
#pragma unroll
        for (int rt = 0; rt < 2; rt++)
#pragma unroll
            for (int nt = 0; nt < 8; nt++) {
                int r = rg * 32 + rt * 16 + l4, c = cg * 64 + nt * 8 + c2;
                sF[r * SF_STR + c]       = acc[rt][nt][0] + sBias[2 * 128 + c];
                sF[r * SF_STR + c + 1]   = acc[rt][nt][1] + sBias[2 * 128 + c + 1];
                sF[(r + 8) * SF_STR + c]     = acc[rt][nt][2] + sBias[2 * 128 + c];
                sF[(r + 8) * SF_STR + c + 1] = acc[rt][nt][3] + sBias[2 * 128 + c + 1];
            }
    }
    __syncthreads();

    // O0 -> X images rows 0..31 (X dead now)
    for (int i = tid; i < 2048; i += NTHREADS) {
        int r = i >> 6, c = (i & 63) * 2;
        img_st2(sm, r, c, sSm[r * SF_STR + c], sSm[r * SF_STR + c + 1]);
    }

    // ===== T0 = O0@Wo0 ; Hset = O0 + relu(T0+bo0) -> images rows 0..31 =====
    {
        load_w(sm, 3, tid);
        float acc[4][4] = {};
        gemm32(xh, xl, wh, wl, wid, lane, acc);
        __syncthreads();                      // all ldmatrix reads of O0 image done
        int rt = wid >> 2, cg = wid & 3;
        int r = rt * 16 + l4;
#pragma unroll
        for (int nt = 0; nt < 4; nt++) {
            int c = cg * 32 + nt * 8 + c2;
            float v0 = sSm[r * SF_STR + c]     + fmaxf(acc[nt][0] + sBias[128 + c], 0.f);
            float v1 = sSm[r * SF_STR + c + 1] + fmaxf(acc[nt][1] + sBias[128 + c + 1], 0.f);
            img_st2(sm, r, c, v0, v1);
            float w0 = sSm[(r + 8) * SF_STR + c]     + fmaxf(acc[nt][2] + sBias[128 + c], 0.f);
            float w1 = sSm[(r + 8) * SF_STR + c + 1] + fmaxf(acc[nt][3] + sBias[128 + c + 1], 0.f);
            img_st2(sm, r + 8, c, w0, w1);
        }
    }

    // ===== K1 = Hset@Wk1 + bk1 -> sSm =====
    {
        load_w(sm, 4, tid);
        float acc[4][4] = {};
        gemm32(xh, xl, wh, wl, wid, lane, acc);
        int rt = wid >> 2, cg = wid & 3;
        int r = rt * 16 + l4;
#pragma unroll
        for (int nt = 0; nt < 4; nt++) {
            int c = cg * 32 + nt * 8 + c2;
            sSm[r * SF_STR + c]       = acc[nt][0] + sBias[3 * 128 + c];
            sSm[r * SF_STR + c + 1]   = acc[nt][1] + sBias[3 * 128 + c + 1];
            sSm[(r + 8) * SF_STR + c]     = acc[nt][2] + sBias[3 * 128 + c];
            sSm[(r + 8) * SF_STR + c + 1] = acc[nt][3] + sBias[3 * 128 + c + 1];
        }
    }

    // ===== V1 = Hset@Wv1 + bv1 -> sV1f (overwrites image region; image dead after) =====
    {
        load_w(sm, 5, tid);
        float acc[4][4] = {};
        gemm32(xh, xl, wh, wl, wid, lane, acc);
        __syncthreads();                      // image reads done before scratch overwrite
        int rt = wid >> 2, cg = wid & 3;
        int r = rt * 16 + l4;
#pragma unroll
        for (int nt = 0; nt < 4; nt++) {
            int c = cg * 32 + nt * 8 + c2;
            sV1f[r * 128 + c]       = acc[nt][0] + sBias[4 * 128 + c];
            sV1f[r * 128 + c + 1]   = acc[nt][1] + sBias[4 * 128 + c + 1];
            sV1f[(r + 8) * 128 + c]     = acc[nt][2] + sBias[4 * 128 + c];
            sV1f[(r + 8) * 128 + c + 1] = acc[nt][3] + sBias[4 * 128 + c + 1];
        }
    }
    __syncthreads();

    // scores1: ((e*4+h)*16+q)*4+k
#pragma unroll 1
    for (int it = 0; it < 8; it++) {
        int idx = tid + it * 256;
        int k = idx & 3, q = (idx >> 2) & 15, h = (idx >> 6) & 3, e = idx >> 8;
        const float4* qv = (const float4*)&sF[(e * 16 + q) * SF_STR + h * 32];
        const float4* kv = (const float4*)&sSm[(e * 4 + k) * SF_STR + h * 32];
        float dot = 0.f;
#pragma unroll
        for (int d4 = 0; d4 < 8; d4++) {
            float4 qq = qv[d4], kk = kv[d4];
            dot += qq.x * kk.x + qq.y * kk.y + qq.z * kk.z + qq.w * kk.w;
        }
        sScr[idx] = dot * SCALE_INV;
    }
    __syncthreads();
    for (int rr = tid; rr < 512; rr += 256) {
        float* p = &sScr[rr * 4];
        float mx = fmaxf(fmaxf(p[0], p[1]), fmaxf(p[2], p[3]));
        float e0 = expf(p[0] - mx), e1 = expf(p[1] - mx), e2 = expf(p[2] - mx), e3 = expf(p[3] - mx);
        float inv = 1.f / (e0 + e1 + e2 + e3);
        p[0] = e0 * inv; p[1] = e1 * inv; p[2] = e2 * inv; p[3] = e3 * inv;
    }
    __syncthreads();

    // O = Q1 + A1@V1f, in place in sF
#pragma unroll 1
    for (int it = 0; it < 64; it++) {
        int idx = tid + it * 256;
        int d = idx & 127, row = idx >> 7;
        int q = row & 15, e = row >> 4, h = d >> 5;
        float o = sF[row * SF_STR + d];
        const float* A = &sScr[((e * 4 + h) * 16 + q) * 4];
        const float* vv = &sV1f[(e * 4) * 128 + d];
#pragma unroll
        for (int k = 0; k < 4; k++) o += A[k] * vv[k * 128];
        sF[row * SF_STR + d] = o;
    }
    __syncthreads();

    // O -> X images (full 128 rows; overwrites sV1f region, now dead)
    for (int i = tid; i < 8192; i += NTHREADS) {
        int r = i >> 6, c = (i & 63) * 2;
        img_st2(sm, r, c, sF[r * SF_STR + c], sF[r * SF_STR + c + 1]);
    }

    // ===== T1 = O@Wo1 ; final = O + relu(T1+bo1) -> sF in place =====
    {
        load_w(sm, 6, tid);
        float acc[2][8][4] = {};
        gemm128(xh, xl, wh, wl, wid, lane, acc);
        int rg = wid >> 1, cg = wid & 1;
#pragma unroll
        for (int rt = 0; rt < 2; rt++)
#pragma unroll
            for (int nt = 0; nt < 8; nt++) {
                int r = rg * 32 + rt * 16 + l4, c = cg * 64 + nt * 8 + c2;
                sF[r * SF_STR + c]       += fmaxf(acc[rt][nt][0] + sBias[5 * 128 + c], 0.f);
                sF[r * SF_STR + c + 1]   += fmaxf(acc[rt][nt][1] + sBias[5 * 128 + c + 1], 0.f);
                sF[(r + 8) * SF_STR + c]     += fmaxf(acc[rt][nt][2] + sBias[5 * 128 + c], 0.f);
                sF[(r + 8) * SF_STR + c + 1] += fmaxf(acc[rt][nt][3] + sBias[5 * 128 + c + 1], 0.f);
            }
    }
    __syncthreads();

    // logits = final @ Wout + bout
#pragma unroll 1
    for (int it = 0; it < 3; it++) {
        int idx = tid + it * 256;
        int c = idx % C_CLS, r = idx / C_CLS;
        float acc = sWo[768 + c];
        const float4* xr = (const float4*)&sF[r * SF_STR];
#pragma unroll
        for (int k4 = 0; k4 < 32; k4++) {
            float4 x = xr[k4];
            acc += x.x * sWo[(k4 * 4 + 0) * C_CLS + c]
                 + x.y * sWo[(k4 * 4 + 1) * C_CLS + c]
                 + x.z * sWo[(k4 * 4 + 2) * C_CLS + c]
                 + x.w * sWo[(k4 * 4 + 3) * C_CLS + c];
        }
        long long off = (long long)(rowbase + r) * C_CLS + c;
        if (off < out_capacity) out[off] = acc;
    }
    long long lab_base = (long long)E_EDGES * S_MEM * C_CLS;
    if (out_capacity >= lab_base + (long long)E_EDGES * S_MEM) {
        for (int r = tid; r < ROWS; r += 256)
            out[lab_base + rowbase + r] = (float)labels[rowbase + r];
    }
}

extern "C" void kernel_launch(void* const* d_in, const int* in_sizes, int n_in,
                              void* d_out, int out_size) {
    const float* Ws[8] = {0,0,0,0,0,0,0,0};
    const float* Bs[8] = {0,0,0,0,0,0,0,0};
    const float* vfeat = 0; const float* Iin = 0;
    const float* Wout = 0;  const float* bout = 0;
    const int* member_idx = 0; const int* labels = 0;
    int wi = 0, bi = 0, n_nodes = 500000;
    for (int i = 0; i < n_in; i++) {
        int sz = in_sizes[i];
        if (sz == 500000 * 128)      { vfeat = (const float*)d_in[i]; n_nodes = sz / D_DIM; }
        else if (sz == E_EDGES * S_MEM) {
            if (!member_idx) member_idx = (const int*)d_in[i];
            else if (!labels) labels = (const int*)d_in[i];
        }
        else if (sz == M_IND * D_DIM) Iin = (const float*)d_in[i];
        else if (sz == D_DIM * C_CLS) Wout = (const float*)d_in[i];
        else if (sz == C_CLS)         bout = (const float*)d_in[i];
        else if (sz == D_DIM * D_DIM) { if (wi < 8) Ws[wi++] = (const float*)d_in[i]; }
        else if (sz == D_DIM)         { if (bi < 8) Bs[bi++] = (const float*)d_in[i]; }
    }
    if (!vfeat || !member_idx || !labels || !Iin || !Wout || !bout || wi != 8 || bi != 8) {
        vfeat = (const float*)d_in[0]; member_idx = (const int*)d_in[1];
        labels = (const int*)d_in[2];  Iin = (const float*)d_in[3];
        Wout = (const float*)d_in[4];  bout = (const float*)d_in[5];
        for (int j = 0; j < 8; j++) { Ws[j] = (const float*)d_in[6 + 2 * j]; Bs[j] = (const float*)d_in[7 + 2 * j]; }
        n_nodes = in_sizes[0] / D_DIM;
    }
    const float *Wq0 = Ws[0], *Wk0 = Ws[1], *Wv0 = Ws[2], *Wo0 = Ws[3];
    const float *Wq1 = Ws[4], *Wk1 = Ws[5], *Wv1 = Ws[6], *Wo1 = Ws[7];
    const float *bq0 = Bs[0], *bk0 = Bs[1], *bv0 = Bs[2], *bo0 = Bs[3];
    const float *bq1 = Bs[4], *bk1 = Bs[5], *bv1 = Bs[6], *bo1 = Bs[7];

    cudaFuncSetAttribute(whatsnet_mma, cudaFuncAttributeMaxDynamicSharedMemorySize, SMEM_TOTAL);

    iq_kernel<<<2, 256>>>(Iin, Wq0, bq0);
    iqb_kernel<<<1, 32>>>(bk0);
    wconv_kernel<<<7, 256>>>(Wk0, Wv0, Wq1, Wo0, Wk1, Wv1, Wo1);

    whatsnet_mma<<<E_EDGES * S_MEM / ROWS, NTHREADS, SMEM_TOTAL>>>(
        vfeat, member_idx, labels, Wout, bout,
        bv0, bo0, bq1, bk1, bv1, bo1,
        (float*)d_out, n_nodes, (long long)out_size);
}